// round 8
// baseline (speedup 1.0000x reference)
#include <cuda_runtime.h>
#include <cstdint>

#define NN      50000
#define EE      800000
#define HH      128
#define LATD    64
#define MAXNODE 200
#define ADJ_SZ   (NN * MAXNODE)
#define NODES_SZ (NN * HH)
#define MU_OFF   (ADJ_SZ + NODES_SZ)
#define LV_OFF   (MU_OFF + LATD)
#define HG_BLOCKS 512

// ---- scratch: static device globals (no allocation). NEVER passed from host. ----
__device__ __align__(16) static int   g_src[EE];
__device__ __align__(16) static int   g_dst[EE];
__device__ __align__(16) static float g_eterm1[EE];
__device__ __align__(16) static float g_eterm2[EE];
__device__ __align__(16) static int   g_srcs[EE];
__device__ __align__(16) static float g_et1s[EE];
__device__ __align__(16) static float g_et2s[EE];
__device__ __align__(16) static int   g_rowptr[NN + 1];
__device__ __align__(16) static int   g_cursor[NN];
__device__ __align__(16) static float g_deg[NN];
__device__ __align__(16) static float g_set1[NN];
__device__ __align__(16) static float g_set2[NN];
__device__ __align__(16) static float g_ve[32];
__device__ __align__(16) static float g_g[2][(size_t)NN * HH];
__device__ __align__(16) static float g_agg[2][(size_t)NN * HH];
__device__ __align__(16) static float g_gs[2][NN];
__device__ __align__(16) static float g_gd[2][NN];
__device__ __align__(16) static float g_ex[EE];
__device__ __align__(16) static float g_hpart[HG_BLOCKS * HH];
__device__ __align__(16) static float g_adj_row[MAXNODE];
__device__ __align__(16) static float g_node_row[HH];
__device__ static int g_idx64;

__device__ __forceinline__ float relu_np(float v) { return v * (float)(v > 0.f); }

// packed f32x2 helpers (FFMA2 is only reachable via PTX fma.rn.f32x2)
__device__ __forceinline__ unsigned long long pack2(float a, float b) {
    unsigned long long r;
    asm("mov.b64 %0, {%1, %2};" : "=l"(r) : "f"(a), "f"(b));
    return r;
}
__device__ __forceinline__ void ffma2(unsigned long long& d, unsigned long long a,
                                      unsigned long long b, unsigned long long c) {
    asm("fma.rn.f32x2 %0, %1, %2, %3;" : "=l"(d) : "l"(a), "l"(b), "l"(c));
}
__device__ __forceinline__ float2 unpack2(unsigned long long v) {
    float2 r;
    asm("mov.b64 {%0, %1}, %2;" : "=f"(r.x), "=f"(r.y) : "l"(v));
    return r;
}

// zero scratch (all blocks) + idx64 detect + ve precompute (block 0)
__global__ void k_pre(const int* __restrict__ ei,
                      const float* __restrict__ We1, const float* __restrict__ ae1,
                      const float* __restrict__ We2, const float* __restrict__ ae2) {
    int stride = gridDim.x * blockDim.x;
    for (int j = blockIdx.x * blockDim.x + threadIdx.x; j < NN; j += stride) {
        g_deg[j] = 0.f; g_set1[j] = 0.f; g_set2[j] = 0.f;
    }
    if (blockIdx.x == 0) {
        __shared__ int nz;
        if (threadIdx.x == 0) nz = 0;
        __syncthreads();
        for (int i = threadIdx.x; i < 1024; i += blockDim.x)
            if (ei[2 * i + 1] != 0) atomicAdd(&nz, 1);
        __syncthreads();
        if (threadIdx.x == 0) g_idx64 = (nz == 0) ? 1 : 0;
        int k = threadIdx.x;
        if (k < 16) {
            float s = 0.f;
            for (int h = 0; h < HH; h++) s += We1[k * HH + h] * ae1[h];
            g_ve[k] = s;
        } else if (k < 32) {
            int kk = k - 16;
            float s = 0.f;
            for (int h = 0; h < HH; h++) s += We2[kk * HH + h] * ae2[h];
            g_ve[16 + kk] = s;
        }
    }
}

__global__ void k_edges(const int* __restrict__ ei_raw, const float* __restrict__ ea) {
    __shared__ float sve[32];
    if (threadIdx.x < 32) sve[threadIdx.x] = g_ve[threadIdx.x];
    __syncthreads();
    int stride = gridDim.x * blockDim.x;
    int idx64 = g_idx64;
    for (int e = blockIdx.x * blockDim.x + threadIdx.x; e < EE; e += stride) {
        int src, dst;
        if (idx64) {
            const long long* pp = (const long long*)ei_raw;
            src = (int)pp[e]; dst = (int)pp[EE + e];
        } else {
            src = ei_raw[e]; dst = ei_raw[EE + e];
        }
        g_src[e] = src; g_dst[e] = dst;
        const float4* ea4 = (const float4*)(ea + (size_t)e * 16);
        float t1 = 0.f, t2 = 0.f;
#pragma unroll
        for (int q = 0; q < 4; q++) {
            float4 v = ea4[q];
            t1 += v.x * sve[q*4+0] + v.y * sve[q*4+1] + v.z * sve[q*4+2] + v.w * sve[q*4+3];
            t2 += v.x * sve[16+q*4+0] + v.y * sve[16+q*4+1] + v.z * sve[16+q*4+2] + v.w * sve[16+q*4+3];
        }
        g_eterm1[e] = t1; g_eterm2[e] = t2;
        atomicAdd(&g_set1[dst], t1);
        atomicAdd(&g_set2[dst], t2);
        atomicAdd(&g_deg[dst], 1.0f);
    }
}

// single-block exclusive prefix sum of deg -> rowptr/cursor; set1/set2 /= max(deg,1) fused
__global__ void __launch_bounds__(1024) k_prefix() {
    __shared__ int sws[32];
    __shared__ int chunk_total;
    int lane = threadIdx.x & 31, wid = threadIdx.x >> 5;
    int running = 0;
    for (int base = 0; base < NN; base += 1024) {
        int i = base + threadIdx.x;
        int v = 0;
        if (i < NN) {
            float dg = g_deg[i];
            float d = fmaxf(dg, 1.0f);
            g_set1[i] /= d;
            g_set2[i] /= d;
            v = (int)dg;
        }
        int x = v;
#pragma unroll
        for (int off = 1; off < 32; off <<= 1) {
            int y = __shfl_up_sync(0xffffffffu, x, off);
            if (lane >= off) x += y;
        }
        if (lane == 31) sws[wid] = x;
        __syncthreads();
        if (wid == 0) {
            int y = sws[lane];
#pragma unroll
            for (int off = 1; off < 32; off <<= 1) {
                int z = __shfl_up_sync(0xffffffffu, y, off);
                if (lane >= off) y += z;
            }
            sws[lane] = y;
            if (lane == 31) chunk_total = y;
        }
        __syncthreads();
        int incl = x + (wid > 0 ? sws[wid - 1] : 0);
        if (i < NN) {
            int excl = running + incl - v;
            g_rowptr[i] = excl;
            g_cursor[i] = excl;
        }
        running += chunk_total;
        __syncthreads();
    }
    if (threadIdx.x == 0) g_rowptr[NN] = running;
}

__global__ void k_scatter() {
    int stride = gridDim.x * blockDim.x;
    for (int e = blockIdx.x * blockDim.x + threadIdx.x; e < EE; e += stride) {
        int dst = g_dst[e];
        int pos = atomicAdd(&g_cursor[dst], 1);
        g_srcs[pos] = g_src[e];
        g_et1s[pos] = g_eterm1[e];
        g_et2s[pos] = g_eterm2[e];
    }
}

// Tiled GEMM: 64x128 output per block, 256 threads, thread tile 4 rows x 8 cols.
// fma.rn.f32x2 packed math. Epilogue fuses gs/gd row dot products.
// layer 0: g_g[0] = x @ W ; layer 1: g_g[1] = relu(g_agg[0] + bias) @ W
__global__ void __launch_bounds__(256) k_gemm128(int layer,
                                                 const float* __restrict__ x,
                                                 const float* __restrict__ W,
                                                 const float* __restrict__ bias,
                                                 const float* __restrict__ as,
                                                 const float* __restrict__ ad) {
    __shared__ float As[32][68];    // [k][row] transposed, padded
    __shared__ float Ws[32][HH];    // [k][col]
    const float* A = (layer == 0) ? x : g_agg[0];
    float* C = g_g[layer];
    int tid = threadIdx.x;
    int tr = tid >> 4;     // 0..15 row group (4 rows)
    int tc = tid & 15;     // 0..15 col group (8 cols)
    int rowBase = blockIdx.x * 64;

    unsigned long long acc2[4][4];
#pragma unroll
    for (int i = 0; i < 4; i++)
#pragma unroll
        for (int j = 0; j < 4; j++) acc2[i][j] = 0ULL;

    for (int chunk = 0; chunk < 4; chunk++) {
        __syncthreads();
        // load A tile (64 rows x 32 k) transposed into As
        for (int t = tid; t < 64 * 8; t += 256) {
            int r  = t >> 3;
            int c4 = t & 7;
            int row = rowBase + r;
            float4 v = make_float4(0.f, 0.f, 0.f, 0.f);
            if (row < NN) {
                v = ((const float4*)A)[(size_t)row * 32 + chunk * 8 + c4];
                if (layer == 1) {
                    float4 b = ((const float4*)bias)[chunk * 8 + c4];
                    v.x = relu_np(v.x + b.x);
                    v.y = relu_np(v.y + b.y);
                    v.z = relu_np(v.z + b.z);
                    v.w = relu_np(v.w + b.w);
                }
            }
            As[c4*4+0][r] = v.x; As[c4*4+1][r] = v.y;
            As[c4*4+2][r] = v.z; As[c4*4+3][r] = v.w;
        }
        // load W tile (32 k x 128 cols)
        for (int t = tid; t < 32 * 32; t += 256) {
            int kk = t >> 5, c4 = t & 31;
            ((float4*)&Ws[kk][0])[c4] = ((const float4*)W)[(size_t)(chunk*32+kk) * 32 + c4];
        }
        __syncthreads();
#pragma unroll 4
        for (int kk = 0; kk < 32; kk++) {
            float4 af = *(const float4*)&As[kk][tr * 4];
            ulonglong2 b01 = *(const ulonglong2*)&Ws[kk][tc * 8];
            ulonglong2 b23 = *(const ulonglong2*)&Ws[kk][tc * 8 + 4];
            unsigned long long a0 = pack2(af.x, af.x);
            unsigned long long a1 = pack2(af.y, af.y);
            unsigned long long a2 = pack2(af.z, af.z);
            unsigned long long a3 = pack2(af.w, af.w);
            ffma2(acc2[0][0], a0, b01.x, acc2[0][0]);
            ffma2(acc2[0][1], a0, b01.y, acc2[0][1]);
            ffma2(acc2[0][2], a0, b23.x, acc2[0][2]);
            ffma2(acc2[0][3], a0, b23.y, acc2[0][3]);
            ffma2(acc2[1][0], a1, b01.x, acc2[1][0]);
            ffma2(acc2[1][1], a1, b01.y, acc2[1][1]);
            ffma2(acc2[1][2], a1, b23.x, acc2[1][2]);
            ffma2(acc2[1][3], a1, b23.y, acc2[1][3]);
            ffma2(acc2[2][0], a2, b01.x, acc2[2][0]);
            ffma2(acc2[2][1], a2, b01.y, acc2[2][1]);
            ffma2(acc2[2][2], a2, b23.x, acc2[2][2]);
            ffma2(acc2[2][3], a2, b23.y, acc2[2][3]);
            ffma2(acc2[3][0], a3, b01.x, acc2[3][0]);
            ffma2(acc2[3][1], a3, b01.y, acc2[3][1]);
            ffma2(acc2[3][2], a3, b23.x, acc2[3][2]);
            ffma2(acc2[3][3], a3, b23.y, acc2[3][3]);
        }
    }

    // epilogue: store C rows + fused gs/gd (reduce over the 16 tc lanes)
    float4 as0 = ((const float4*)as)[tc * 2];
    float4 as1 = ((const float4*)as)[tc * 2 + 1];
    float4 ad0 = ((const float4*)ad)[tc * 2];
    float4 ad1 = ((const float4*)ad)[tc * 2 + 1];
#pragma unroll
    for (int i = 0; i < 4; i++) {
        int row = rowBase + tr * 4 + i;
        bool ok = (row < NN);
        float2 p0 = unpack2(acc2[i][0]);
        float2 p1 = unpack2(acc2[i][1]);
        float2 p2 = unpack2(acc2[i][2]);
        float2 p3 = unpack2(acc2[i][3]);
        float4 o0 = make_float4(p0.x, p0.y, p1.x, p1.y);
        float4 o1 = make_float4(p2.x, p2.y, p3.x, p3.y);
        if (ok) {
            ((float4*)C)[(size_t)row * 32 + tc * 2]     = o0;
            ((float4*)C)[(size_t)row * 32 + tc * 2 + 1] = o1;
        }
        float s = o0.x*as0.x + o0.y*as0.y + o0.z*as0.z + o0.w*as0.w
                + o1.x*as1.x + o1.y*as1.y + o1.z*as1.z + o1.w*as1.w;
        float d = o0.x*ad0.x + o0.y*ad0.y + o0.z*ad0.z + o0.w*ad0.w
                + o1.x*ad1.x + o1.y*ad1.y + o1.z*ad1.z + o1.w*ad1.w;
#pragma unroll
        for (int off = 1; off < 16; off <<= 1) {
            s += __shfl_xor_sync(0xffffffffu, s, off);
            d += __shfl_xor_sync(0xffffffffu, d, off);
        }
        if (ok && tc == 0) {
            g_gs[layer][row] = s;
            g_gd[layer][row] = d;
        }
    }
}

// Fused attention softmax + aggregation: one warp per node, zero atomics, MLP-4 gather
__global__ void __launch_bounds__(256) k_aggfused(int layer) {
    int node = blockIdx.x * 8 + (threadIdx.x >> 5);
    int lane = threadIdx.x & 31;
    if (node >= NN) return;
    const float* gs  = g_gs[layer];
    const float* gd  = g_gd[layer];
    const float* ets = layer ? g_et2s : g_et1s;
    const float* set = layer ? g_set2 : g_set1;
    const float* gp  = g_g[layer];
    float* aggp      = g_agg[layer];

    int beg = g_rowptr[node], end = g_rowptr[node + 1];
    float gd_i = gd[node];

    float a_self = gs[node] + gd_i + set[node];
    a_self = a_self > 0.f ? a_self : 0.2f * a_self;
    float ex_self = expf(a_self);

    float densum = 0.f;
    for (int j = beg + lane; j < end; j += 32) {
        int src = g_srcs[j];
        float a = gs[src] + gd_i + ets[j];
        a = a > 0.f ? a : 0.2f * a;
        float ex = expf(a);
        g_ex[j] = ex;
        densum += ex;
    }
#pragma unroll
    for (int off = 16; off > 0; off >>= 1)
        densum += __shfl_xor_sync(0xffffffffu, densum, off);
    float inv = 1.0f / (densum + ex_self);

    float w = ex_self * inv;
    float4 v = *(const float4*)(gp + (size_t)node * HH + lane * 4);
    float4 acc = make_float4(w * v.x, w * v.y, w * v.z, w * v.w);

    int j = beg;
    for (; j + 4 <= end; j += 4) {
        int s0 = g_srcs[j], s1 = g_srcs[j+1], s2 = g_srcs[j+2], s3 = g_srcs[j+3];
        float w0 = g_ex[j] * inv, w1 = g_ex[j+1] * inv,
              w2 = g_ex[j+2] * inv, w3 = g_ex[j+3] * inv;
        float4 u0 = *(const float4*)(gp + (size_t)s0 * HH + lane * 4);
        float4 u1 = *(const float4*)(gp + (size_t)s1 * HH + lane * 4);
        float4 u2 = *(const float4*)(gp + (size_t)s2 * HH + lane * 4);
        float4 u3 = *(const float4*)(gp + (size_t)s3 * HH + lane * 4);
        acc.x += w0*u0.x + w1*u1.x + w2*u2.x + w3*u3.x;
        acc.y += w0*u0.y + w1*u1.y + w2*u2.y + w3*u3.y;
        acc.z += w0*u0.z + w1*u1.z + w2*u2.z + w3*u3.z;
        acc.w += w0*u0.w + w1*u1.w + w2*u2.w + w3*u3.w;
    }
    for (; j < end; j++) {
        float wj = g_ex[j] * inv;
        int src  = g_srcs[j];
        float4 u = *(const float4*)(gp + (size_t)src * HH + lane * 4);
        acc.x += wj * u.x;
        acc.y += wj * u.y;
        acc.z += wj * u.z;
        acc.w += wj * u.w;
    }
    *(float4*)(aggp + (size_t)node * HH + lane * 4) = acc;
}

__global__ void k_hgsum(const float* __restrict__ b2) {
    __shared__ float sh[HH];
    int c = threadIdx.x & 127;
    int half = threadIdx.x >> 7;
    float bb = b2[c];
    float s = 0.f;
    for (int i = blockIdx.x * 2 + half; i < NN; i += gridDim.x * 2)
        s += relu_np(g_agg[1][(size_t)i * HH + c] + bb);
    if (half == 1) sh[c] = s;
    __syncthreads();
    if (half == 0) g_hpart[blockIdx.x * HH + c] = s + sh[c];
}

__global__ void k_head(const float* __restrict__ muW, const float* __restrict__ mub,
                       const float* __restrict__ lvW, const float* __restrict__ lvb,
                       const float* __restrict__ eps,
                       const float* __restrict__ decW, const float* __restrict__ decb,
                       const float* __restrict__ aW1, const float* __restrict__ ab1,
                       const float* __restrict__ aW2, const float* __restrict__ ab2,
                       const float* __restrict__ nW1, const float* __restrict__ nb1,
                       const float* __restrict__ nW2, const float* __restrict__ nb2,
                       float* __restrict__ out) {
    __shared__ float hgm[HH], z[LATD], hd[HH], tmp[HH];
    int t = threadIdx.x;
    if (t < HH) {
        float s = 0.f;
        for (int b = 0; b < HG_BLOCKS; b++) s += g_hpart[b * HH + t];
        hgm[t] = s * (1.0f / (float)NN);
    }
    __syncthreads();
    if (t < LATD) {
        float m = mub[t], l = lvb[t];
        for (int k = 0; k < HH; k++) { m += hgm[k] * muW[k * LATD + t]; l += hgm[k] * lvW[k * LATD + t]; }
        out[MU_OFF + t] = m;
        out[LV_OFF + t] = l;
        z[t] = m + eps[t] * expf(0.5f * l);
    }
    __syncthreads();
    if (t < HH) {
        float s = decb[t];
        for (int j = 0; j < LATD; j++) s += z[j] * decW[j * HH + t];
        hd[t] = relu_np(s);
    }
    __syncthreads();
    if (t < HH) {
        float s = ab1[t];
        for (int k = 0; k < HH; k++) s += hd[k] * aW1[k * HH + t];
        tmp[t] = relu_np(s);
    }
    __syncthreads();
    for (int m = t; m < MAXNODE; m += blockDim.x) {
        float s = ab2[m];
        for (int k = 0; k < HH; k++) s += tmp[k] * aW2[k * MAXNODE + m];
        g_adj_row[m] = s;
    }
    __syncthreads();
    if (t < HH) {
        float s = nb1[t];
        for (int k = 0; k < HH; k++) s += hd[k] * nW1[k * HH + t];
        tmp[t] = relu_np(s);
    }
    __syncthreads();
    if (t < HH) {
        float s = nb2[t];
        for (int k = 0; k < HH; k++) s += tmp[k] * nW2[k * HH + t];
        g_node_row[t] = s;
    }
}

__global__ void k_fill(float4* __restrict__ out4) {
    __shared__ float4 sadj[50];
    __shared__ float4 snd[32];
    int t = threadIdx.x;
    if (t < 50) sadj[t] = ((const float4*)g_adj_row)[t];
    else if (t < 82) snd[t - 50] = ((const float4*)g_node_row)[t - 50];
    __syncthreads();
    const int ADJ4 = ADJ_SZ / 4;
    const int TOT4 = (ADJ_SZ + NODES_SZ) / 4;
    int stride = gridDim.x * blockDim.x;
    for (int i = blockIdx.x * blockDim.x + t; i < TOT4; i += stride) {
        float4 v;
        if (i < ADJ4) v = sadj[i % 50];
        else          v = snd[(i - ADJ4) & 31];
        out4[i] = v;
    }
}

extern "C" void kernel_launch(void* const* d_in, const int* in_sizes, int n_in,
                              void* d_out, int out_size) {
    const float* x   = (const float*)d_in[0];
    const int*   ei  = (const int*)  d_in[1];
    const float* ea  = (const float*)d_in[2];
    const float* eps = (const float*)d_in[3];
    int p = n_in - 26;
    if (p < 4) p = 4;
    if (p > 5) p = (in_sizes[4] == 1) ? 5 : 4;
    const float* W1   = (const float*)d_in[p + 0];
    const float* as1  = (const float*)d_in[p + 1];
    const float* ad1  = (const float*)d_in[p + 2];
    const float* We1  = (const float*)d_in[p + 3];
    const float* ae1  = (const float*)d_in[p + 4];
    const float* b1   = (const float*)d_in[p + 5];
    const float* W2   = (const float*)d_in[p + 6];
    const float* as2  = (const float*)d_in[p + 7];
    const float* ad2  = (const float*)d_in[p + 8];
    const float* We2  = (const float*)d_in[p + 9];
    const float* ae2  = (const float*)d_in[p + 10];
    const float* b2   = (const float*)d_in[p + 11];
    const float* muW  = (const float*)d_in[p + 12];
    const float* mub  = (const float*)d_in[p + 13];
    const float* lvW  = (const float*)d_in[p + 14];
    const float* lvb  = (const float*)d_in[p + 15];
    const float* decW = (const float*)d_in[p + 16];
    const float* decb = (const float*)d_in[p + 17];
    const float* aW1  = (const float*)d_in[p + 18];
    const float* ab1  = (const float*)d_in[p + 19];
    const float* aW2  = (const float*)d_in[p + 20];
    const float* ab2  = (const float*)d_in[p + 21];
    const float* nW1  = (const float*)d_in[p + 22];
    const float* nb1  = (const float*)d_in[p + 23];
    const float* nW2  = (const float*)d_in[p + 24];
    const float* nb2  = (const float*)d_in[p + 25];
    float* out = (float*)d_out;

    k_pre<<<256, 256>>>(ei, We1, ae1, We2, ae2);
    k_edges<<<2048, 256>>>(ei, ea);
    k_prefix<<<1, 1024>>>();
    k_scatter<<<2048, 256>>>();

    int gemm_blocks = (NN + 63) / 64;
    int agg_blocks = (NN + 7) / 8;

    k_gemm128<<<gemm_blocks, 256>>>(0, x, W1, b1, as1, ad1);
    k_aggfused<<<agg_blocks, 256>>>(0);

    k_gemm128<<<gemm_blocks, 256>>>(1, x, W2, b1, as2, ad2);
    k_aggfused<<<agg_blocks, 256>>>(1);

    k_hgsum<<<HG_BLOCKS, 256>>>(b2);
    k_head<<<1, 256>>>(muW, mub, lvW, lvb, eps, decW, decb,
                       aW1, ab1, aW2, ab2, nW1, nb1, nW2, nb2, out);
    k_fill<<<2048, 256>>>((float4*)out);
}

// round 9
// speedup vs baseline: 1.1488x; 1.1488x over previous
#include <cuda_runtime.h>
#include <cstdint>

#define NN      50000
#define EE      800000
#define HH      128
#define LATD    64
#define MAXNODE 200
#define ADJ_SZ   (NN * MAXNODE)
#define NODES_SZ (NN * HH)
#define MU_OFF   (ADJ_SZ + NODES_SZ)
#define LV_OFF   (MU_OFF + LATD)
#define HG_BLOCKS 512

// ---- scratch: static device globals (no allocation). NEVER passed from host. ----
__device__ __align__(16) static int   g_srcs[EE];    // CSR-ordered src
__device__ __align__(16) static float g_et1s[EE];    // CSR-ordered eterm1
__device__ __align__(16) static float g_et2s[EE];    // CSR-ordered eterm2
__device__ __align__(16) static int   g_rowptr[NN + 1];
__device__ __align__(16) static int   g_cursor[NN];
__device__ __align__(16) static float g_deg[NN];
__device__ __align__(16) static float g_set1[NN];
__device__ __align__(16) static float g_set2[NN];
__device__ __align__(16) static float g_ve[32];
__device__ __align__(16) static float g_g[2][(size_t)NN * HH];
__device__ __align__(16) static float g_agg[2][(size_t)NN * HH];
__device__ __align__(16) static float g_gs[2][NN];
__device__ __align__(16) static float g_gd[2][NN];
__device__ __align__(16) static float g_ex[EE];
__device__ __align__(16) static float g_hpart[HG_BLOCKS * HH];
__device__ __align__(16) static float g_adj_row[MAXNODE];
__device__ __align__(16) static float g_node_row[HH];
__device__ static int g_idx64;

__device__ __forceinline__ float relu_np(float v) { return v * (float)(v > 0.f); }

// zero scratch (all blocks) + idx64 detect + ve precompute (block 0)
__global__ void k_pre(const int* __restrict__ ei,
                      const float* __restrict__ We1, const float* __restrict__ ae1,
                      const float* __restrict__ We2, const float* __restrict__ ae2) {
    int stride = gridDim.x * blockDim.x;
    for (int j = blockIdx.x * blockDim.x + threadIdx.x; j < NN; j += stride) {
        g_deg[j] = 0.f; g_set1[j] = 0.f; g_set2[j] = 0.f;
    }
    if (blockIdx.x == 0) {
        __shared__ int nz;
        if (threadIdx.x == 0) nz = 0;
        __syncthreads();
        for (int i = threadIdx.x; i < 1024; i += blockDim.x)
            if (ei[2 * i + 1] != 0) atomicAdd(&nz, 1);
        __syncthreads();
        if (threadIdx.x == 0) g_idx64 = (nz == 0) ? 1 : 0;
        int k = threadIdx.x;
        if (k < 16) {
            float s = 0.f;
            for (int h = 0; h < HH; h++) s += We1[k * HH + h] * ae1[h];
            g_ve[k] = s;
        } else if (k < 32) {
            int kk = k - 16;
            float s = 0.f;
            for (int h = 0; h < HH; h++) s += We2[kk * HH + h] * ae2[h];
            g_ve[16 + kk] = s;
        }
    }
}

// degree histogram (reads only the dst row of edge_index)
__global__ void k_deg(const int* __restrict__ ei_raw) {
    int stride = gridDim.x * blockDim.x;
    int idx64 = g_idx64;
    for (int e = blockIdx.x * blockDim.x + threadIdx.x; e < EE; e += stride) {
        int dst;
        if (idx64) dst = (int)((const long long*)ei_raw)[EE + e];
        else       dst = ei_raw[EE + e];
        atomicAdd(&g_deg[dst], 1.0f);
    }
}

// single-block exclusive prefix sum of deg -> rowptr, cursor
__global__ void __launch_bounds__(1024) k_prefix() {
    __shared__ int sws[32];
    __shared__ int chunk_total;
    int lane = threadIdx.x & 31, wid = threadIdx.x >> 5;
    int running = 0;
    for (int base = 0; base < NN; base += 1024) {
        int i = base + threadIdx.x;
        int v = (i < NN) ? (int)g_deg[i] : 0;
        int x = v;
#pragma unroll
        for (int off = 1; off < 32; off <<= 1) {
            int y = __shfl_up_sync(0xffffffffu, x, off);
            if (lane >= off) x += y;
        }
        if (lane == 31) sws[wid] = x;
        __syncthreads();
        if (wid == 0) {
            int y = sws[lane];
#pragma unroll
            for (int off = 1; off < 32; off <<= 1) {
                int z = __shfl_up_sync(0xffffffffu, y, off);
                if (lane >= off) y += z;
            }
            sws[lane] = y;
            if (lane == 31) chunk_total = y;
        }
        __syncthreads();
        int incl = x + (wid > 0 ? sws[wid - 1] : 0);
        if (i < NN) {
            int excl = running + incl - v;
            g_rowptr[i] = excl;
            g_cursor[i] = excl;
        }
        running += chunk_total;
        __syncthreads();
    }
    if (threadIdx.x == 0) g_rowptr[NN] = running;
}

// fused: read ei + ea once; compute eterm1/2; write DIRECTLY into CSR slots;
// accumulate set1/set2 segment sums.
__global__ void k_scatter(const int* __restrict__ ei_raw, const float* __restrict__ ea) {
    __shared__ float sve[32];
    if (threadIdx.x < 32) sve[threadIdx.x] = g_ve[threadIdx.x];
    __syncthreads();
    int stride = gridDim.x * blockDim.x;
    int idx64 = g_idx64;
    for (int e = blockIdx.x * blockDim.x + threadIdx.x; e < EE; e += stride) {
        int src, dst;
        if (idx64) {
            const long long* pp = (const long long*)ei_raw;
            src = (int)pp[e]; dst = (int)pp[EE + e];
        } else {
            src = ei_raw[e]; dst = ei_raw[EE + e];
        }
        const float4* ea4 = (const float4*)(ea + (size_t)e * 16);
        float t1 = 0.f, t2 = 0.f;
#pragma unroll
        for (int q = 0; q < 4; q++) {
            float4 v = ea4[q];
            t1 += v.x * sve[q*4+0] + v.y * sve[q*4+1] + v.z * sve[q*4+2] + v.w * sve[q*4+3];
            t2 += v.x * sve[16+q*4+0] + v.y * sve[16+q*4+1] + v.z * sve[16+q*4+2] + v.w * sve[16+q*4+3];
        }
        int pos = atomicAdd(&g_cursor[dst], 1);
        g_srcs[pos] = src;
        g_et1s[pos] = t1;
        g_et2s[pos] = t2;
        atomicAdd(&g_set1[dst], t1);
        atomicAdd(&g_set2[dst], t2);
    }
}

// layer 0: g_g[0] = x @ W ; layer 1: g_g[1] = relu(g_agg[0] + bias) @ W
// 8 warps, 4 rows/warp in registers, shfl broadcast; W via 32KB static smem.
// Epilogue fuses gs/gd row dot products.   (Round-7 known-good version)
__global__ void __launch_bounds__(256) k_gemm128(int layer,
                                                 const float* __restrict__ x,
                                                 const float* __restrict__ W,
                                                 const float* __restrict__ bias,
                                                 const float* __restrict__ as,
                                                 const float* __restrict__ ad) {
    __shared__ float4 Ws4[64 * 32];
    const float* A = (layer == 0) ? x : g_agg[0];
    float*       C = g_g[layer];
    int tid  = threadIdx.x;
    int warp = tid >> 5, lane = tid & 31;
    int row0 = blockIdx.x * 32 + warp * 4;

    float4 bsel = make_float4(0.f, 0.f, 0.f, 0.f);
    if (layer == 1) bsel = ((const float4*)bias)[lane];
    float4 as4 = ((const float4*)as)[lane];
    float4 ad4 = ((const float4*)ad)[lane];

    float4 av[4];
#pragma unroll
    for (int r = 0; r < 4; r++) {
        int row = row0 + r;
        float4 v = make_float4(0.f, 0.f, 0.f, 0.f);
        if (row < NN) {
            v = ((const float4*)A)[(size_t)row * 32 + lane];
            if (layer == 1) {
                v.x = relu_np(v.x + bsel.x);
                v.y = relu_np(v.y + bsel.y);
                v.z = relu_np(v.z + bsel.z);
                v.w = relu_np(v.w + bsel.w);
            }
        }
        av[r] = v;
    }

    float4 acc[4];
#pragma unroll
    for (int r = 0; r < 4; r++) acc[r] = make_float4(0.f, 0.f, 0.f, 0.f);

#pragma unroll
    for (int chunk = 0; chunk < 2; chunk++) {
        const float4* Wc = (const float4*)W + chunk * 64 * 32;
        __syncthreads();
        for (int i = tid; i < 64 * 32; i += 256) Ws4[i] = Wc[i];
        __syncthreads();
#pragma unroll
        for (int kk = 0; kk < 64; kk++) {
            int k = chunk * 64 + kk;
            int srcLane = k >> 2;
            const int sel = k & 3;
            float4 w4 = Ws4[kk * 32 + lane];
#pragma unroll
            for (int r = 0; r < 4; r++) {
                float av_sel = (sel == 0) ? av[r].x : (sel == 1) ? av[r].y
                             : (sel == 2) ? av[r].z : av[r].w;
                float a_k = __shfl_sync(0xffffffffu, av_sel, srcLane);
                acc[r].x += a_k * w4.x;
                acc[r].y += a_k * w4.y;
                acc[r].z += a_k * w4.z;
                acc[r].w += a_k * w4.w;
            }
        }
    }

#pragma unroll
    for (int r = 0; r < 4; r++) {
        int row = row0 + r;
        if (row < NN) {
            ((float4*)C)[(size_t)row * 32 + lane] = acc[r];
            float s = acc[r].x * as4.x + acc[r].y * as4.y + acc[r].z * as4.z + acc[r].w * as4.w;
            float d = acc[r].x * ad4.x + acc[r].y * ad4.y + acc[r].z * ad4.z + acc[r].w * ad4.w;
#pragma unroll
            for (int off = 16; off > 0; off >>= 1) {
                s += __shfl_xor_sync(0xffffffffu, s, off);
                d += __shfl_xor_sync(0xffffffffu, d, off);
            }
            if (lane == 0) {
                g_gs[layer][row] = s;
                g_gd[layer][row] = d;
            }
        }
    }
}

// Fused attention softmax + aggregation: one warp per node, zero atomics, MLP-4 gather.
// set / max(deg,1) folded in here (one scalar load per node).
__global__ void __launch_bounds__(256) k_aggfused(int layer) {
    int node = blockIdx.x * 8 + (threadIdx.x >> 5);
    int lane = threadIdx.x & 31;
    if (node >= NN) return;
    const float* gs  = g_gs[layer];
    const float* gd  = g_gd[layer];
    const float* ets = layer ? g_et2s : g_et1s;
    const float* set = layer ? g_set2 : g_set1;
    const float* gp  = g_g[layer];
    float* aggp      = g_agg[layer];

    int beg = g_rowptr[node], end = g_rowptr[node + 1];
    float gd_i = gd[node];

    float et_self = set[node] / fmaxf(g_deg[node], 1.0f);
    float a_self = gs[node] + gd_i + et_self;
    a_self = a_self > 0.f ? a_self : 0.2f * a_self;
    float ex_self = expf(a_self);

    float densum = 0.f;
    for (int j = beg + lane; j < end; j += 32) {
        int src = g_srcs[j];
        float a = gs[src] + gd_i + ets[j];
        a = a > 0.f ? a : 0.2f * a;
        float ex = expf(a);
        g_ex[j] = ex;
        densum += ex;
    }
#pragma unroll
    for (int off = 16; off > 0; off >>= 1)
        densum += __shfl_xor_sync(0xffffffffu, densum, off);
    float inv = 1.0f / (densum + ex_self);

    float w = ex_self * inv;
    float4 v = *(const float4*)(gp + (size_t)node * HH + lane * 4);
    float4 acc = make_float4(w * v.x, w * v.y, w * v.z, w * v.w);

    int j = beg;
    for (; j + 4 <= end; j += 4) {
        int s0 = g_srcs[j], s1 = g_srcs[j+1], s2 = g_srcs[j+2], s3 = g_srcs[j+3];
        float w0 = g_ex[j] * inv, w1 = g_ex[j+1] * inv,
              w2 = g_ex[j+2] * inv, w3 = g_ex[j+3] * inv;
        float4 u0 = *(const float4*)(gp + (size_t)s0 * HH + lane * 4);
        float4 u1 = *(const float4*)(gp + (size_t)s1 * HH + lane * 4);
        float4 u2 = *(const float4*)(gp + (size_t)s2 * HH + lane * 4);
        float4 u3 = *(const float4*)(gp + (size_t)s3 * HH + lane * 4);
        acc.x += w0*u0.x + w1*u1.x + w2*u2.x + w3*u3.x;
        acc.y += w0*u0.y + w1*u1.y + w2*u2.y + w3*u3.y;
        acc.z += w0*u0.z + w1*u1.z + w2*u2.z + w3*u3.z;
        acc.w += w0*u0.w + w1*u1.w + w2*u2.w + w3*u3.w;
    }
    for (; j < end; j++) {
        float wj = g_ex[j] * inv;
        int src  = g_srcs[j];
        float4 u = *(const float4*)(gp + (size_t)src * HH + lane * 4);
        acc.x += wj * u.x;
        acc.y += wj * u.y;
        acc.z += wj * u.z;
        acc.w += wj * u.w;
    }
    *(float4*)(aggp + (size_t)node * HH + lane * 4) = acc;
}

__global__ void k_hgsum(const float* __restrict__ b2) {
    __shared__ float sh[HH];
    int c = threadIdx.x & 127;
    int half = threadIdx.x >> 7;
    float bb = b2[c];
    float s = 0.f;
    for (int i = blockIdx.x * 2 + half; i < NN; i += gridDim.x * 2)
        s += relu_np(g_agg[1][(size_t)i * HH + c] + bb);
    if (half == 1) sh[c] = s;
    __syncthreads();
    if (half == 0) g_hpart[blockIdx.x * HH + c] = s + sh[c];
}

__global__ void k_head(const float* __restrict__ muW, const float* __restrict__ mub,
                       const float* __restrict__ lvW, const float* __restrict__ lvb,
                       const float* __restrict__ eps,
                       const float* __restrict__ decW, const float* __restrict__ decb,
                       const float* __restrict__ aW1, const float* __restrict__ ab1,
                       const float* __restrict__ aW2, const float* __restrict__ ab2,
                       const float* __restrict__ nW1, const float* __restrict__ nb1,
                       const float* __restrict__ nW2, const float* __restrict__ nb2,
                       float* __restrict__ out) {
    __shared__ float hgm[HH], z[LATD], hd[HH], tmp[HH];
    int t = threadIdx.x;
    if (t < HH) {
        float s = 0.f;
        for (int b = 0; b < HG_BLOCKS; b++) s += g_hpart[b * HH + t];
        hgm[t] = s * (1.0f / (float)NN);
    }
    __syncthreads();
    if (t < LATD) {
        float m = mub[t], l = lvb[t];
        for (int k = 0; k < HH; k++) { m += hgm[k] * muW[k * LATD + t]; l += hgm[k] * lvW[k * LATD + t]; }
        out[MU_OFF + t] = m;
        out[LV_OFF + t] = l;
        z[t] = m + eps[t] * expf(0.5f * l);
    }
    __syncthreads();
    if (t < HH) {
        float s = decb[t];
        for (int j = 0; j < LATD; j++) s += z[j] * decW[j * HH + t];
        hd[t] = relu_np(s);
    }
    __syncthreads();
    if (t < HH) {
        float s = ab1[t];
        for (int k = 0; k < HH; k++) s += hd[k] * aW1[k * HH + t];
        tmp[t] = relu_np(s);
    }
    __syncthreads();
    for (int m = t; m < MAXNODE; m += blockDim.x) {
        float s = ab2[m];
        for (int k = 0; k < HH; k++) s += tmp[k] * aW2[k * MAXNODE + m];
        g_adj_row[m] = s;
    }
    __syncthreads();
    if (t < HH) {
        float s = nb1[t];
        for (int k = 0; k < HH; k++) s += hd[k] * nW1[k * HH + t];
        tmp[t] = relu_np(s);
    }
    __syncthreads();
    if (t < HH) {
        float s = nb2[t];
        for (int k = 0; k < HH; k++) s += tmp[k] * nW2[k * HH + t];
        g_node_row[t] = s;
    }
}

__global__ void k_fill(float4* __restrict__ out4) {
    __shared__ float4 sadj[50];
    __shared__ float4 snd[32];
    int t = threadIdx.x;
    if (t < 50) sadj[t] = ((const float4*)g_adj_row)[t];
    else if (t < 82) snd[t - 50] = ((const float4*)g_node_row)[t - 50];
    __syncthreads();
    const int ADJ4 = ADJ_SZ / 4;
    const int TOT4 = (ADJ_SZ + NODES_SZ) / 4;
    int stride = gridDim.x * blockDim.x;
    for (int i = blockIdx.x * blockDim.x + t; i < TOT4; i += stride) {
        float4 v;
        if (i < ADJ4) v = sadj[i % 50];
        else          v = snd[(i - ADJ4) & 31];
        out4[i] = v;
    }
}

extern "C" void kernel_launch(void* const* d_in, const int* in_sizes, int n_in,
                              void* d_out, int out_size) {
    const float* x   = (const float*)d_in[0];
    const int*   ei  = (const int*)  d_in[1];
    const float* ea  = (const float*)d_in[2];
    const float* eps = (const float*)d_in[3];
    int p = n_in - 26;
    if (p < 4) p = 4;
    if (p > 5) p = (in_sizes[4] == 1) ? 5 : 4;
    const float* W1   = (const float*)d_in[p + 0];
    const float* as1  = (const float*)d_in[p + 1];
    const float* ad1  = (const float*)d_in[p + 2];
    const float* We1  = (const float*)d_in[p + 3];
    const float* ae1  = (const float*)d_in[p + 4];
    const float* b1   = (const float*)d_in[p + 5];
    const float* W2   = (const float*)d_in[p + 6];
    const float* as2  = (const float*)d_in[p + 7];
    const float* ad2  = (const float*)d_in[p + 8];
    const float* We2  = (const float*)d_in[p + 9];
    const float* ae2  = (const float*)d_in[p + 10];
    const float* b2   = (const float*)d_in[p + 11];
    const float* muW  = (const float*)d_in[p + 12];
    const float* mub  = (const float*)d_in[p + 13];
    const float* lvW  = (const float*)d_in[p + 14];
    const float* lvb  = (const float*)d_in[p + 15];
    const float* decW = (const float*)d_in[p + 16];
    const float* decb = (const float*)d_in[p + 17];
    const float* aW1  = (const float*)d_in[p + 18];
    const float* ab1  = (const float*)d_in[p + 19];
    const float* aW2  = (const float*)d_in[p + 20];
    const float* ab2  = (const float*)d_in[p + 21];
    const float* nW1  = (const float*)d_in[p + 22];
    const float* nb1  = (const float*)d_in[p + 23];
    const float* nW2  = (const float*)d_in[p + 24];
    const float* nb2  = (const float*)d_in[p + 25];
    float* out = (float*)d_out;

    k_pre<<<256, 256>>>(ei, We1, ae1, We2, ae2);
    k_deg<<<2048, 256>>>(ei);
    k_prefix<<<1, 1024>>>();
    k_scatter<<<2048, 256>>>(ei, ea);

    int gemm_blocks = (NN + 31) / 32;
    int agg_blocks = (NN + 7) / 8;

    k_gemm128<<<gemm_blocks, 256>>>(0, x, W1, b1, as1, ad1);
    k_aggfused<<<agg_blocks, 256>>>(0);

    k_gemm128<<<gemm_blocks, 256>>>(1, x, W2, b1, as2, ad2);
    k_aggfused<<<agg_blocks, 256>>>(1);

    k_hgsum<<<HG_BLOCKS, 256>>>(b2);
    k_head<<<1, 256>>>(muW, mub, lvW, lvb, eps, decW, decb,
                       aW1, ab1, aW2, ab2, nW1, nb1, nW2, nb2, out);
    k_fill<<<2048, 256>>>((float4*)out);
}

// round 10
// speedup vs baseline: 1.1499x; 1.0009x over previous
#include <cuda_runtime.h>
#include <mma.h>
#include <cstdint>

using namespace nvcuda;

#define NN      50000
#define NN_PAD  50048            // 782 * 64
#define EE      800000
#define HH      128
#define LATD    64
#define MAXNODE 200
#define ADJ_SZ   (NN * MAXNODE)
#define NODES_SZ (NN * HH)
#define MU_OFF   (ADJ_SZ + NODES_SZ)
#define LV_OFF   (MU_OFF + LATD)
#define HG_BLOCKS 512

// ---- scratch: static device globals (no allocation). NEVER passed from host. ----
__device__ __align__(16) static int4  g_csr[EE];     // {src, et1, et2, ex}
__device__ __align__(16) static int   g_rowptr[NN + 1];
__device__ __align__(16) static int   g_cursor[NN];
__device__ __align__(16) static float g_deg[NN];
__device__ __align__(16) static float g_set1[NN];
__device__ __align__(16) static float g_set2[NN];
__device__ __align__(16) static float g_ve[32];
__device__ __align__(16) static float g_g[2][(size_t)NN_PAD * HH];
__device__ __align__(16) static float g_agg[2][(size_t)NN_PAD * HH];
__device__ __align__(16) static float g_gs[2][NN];
__device__ __align__(16) static float g_gd[2][NN];
__device__ __align__(16) static float g_hpart[HG_BLOCKS * HH];
__device__ __align__(16) static float g_adj_row[MAXNODE];
__device__ __align__(16) static float g_node_row[HH];
__device__ static int g_idx64;

__device__ __forceinline__ float relu_np(float v) { return v * (float)(v > 0.f); }

// zero scratch (all blocks) + idx64 detect + ve precompute (block 0)
__global__ void k_pre(const int* __restrict__ ei,
                      const float* __restrict__ We1, const float* __restrict__ ae1,
                      const float* __restrict__ We2, const float* __restrict__ ae2) {
    int stride = gridDim.x * blockDim.x;
    for (int j = blockIdx.x * blockDim.x + threadIdx.x; j < NN; j += stride) {
        g_deg[j] = 0.f; g_set1[j] = 0.f; g_set2[j] = 0.f;
    }
    if (blockIdx.x == 0) {
        __shared__ int nz;
        if (threadIdx.x == 0) nz = 0;
        __syncthreads();
        for (int i = threadIdx.x; i < 1024; i += blockDim.x)
            if (ei[2 * i + 1] != 0) atomicAdd(&nz, 1);
        __syncthreads();
        if (threadIdx.x == 0) g_idx64 = (nz == 0) ? 1 : 0;
        int k = threadIdx.x;
        if (k < 16) {
            float s = 0.f;
            for (int h = 0; h < HH; h++) s += We1[k * HH + h] * ae1[h];
            g_ve[k] = s;
        } else if (k < 32) {
            int kk = k - 16;
            float s = 0.f;
            for (int h = 0; h < HH; h++) s += We2[kk * HH + h] * ae2[h];
            g_ve[16 + kk] = s;
        }
    }
}

// degree histogram (reads only the dst row of edge_index)
__global__ void k_deg(const int* __restrict__ ei_raw) {
    int stride = gridDim.x * blockDim.x;
    int idx64 = g_idx64;
    for (int e = blockIdx.x * blockDim.x + threadIdx.x; e < EE; e += stride) {
        int dst;
        if (idx64) dst = (int)((const long long*)ei_raw)[EE + e];
        else       dst = ei_raw[EE + e];
        atomicAdd(&g_deg[dst], 1.0f);
    }
}

// single-block exclusive prefix sum of deg -> rowptr, cursor
__global__ void __launch_bounds__(1024) k_prefix() {
    __shared__ int sws[32];
    __shared__ int chunk_total;
    int lane = threadIdx.x & 31, wid = threadIdx.x >> 5;
    int running = 0;
    for (int base = 0; base < NN; base += 1024) {
        int i = base + threadIdx.x;
        int v = (i < NN) ? (int)g_deg[i] : 0;
        int x = v;
#pragma unroll
        for (int off = 1; off < 32; off <<= 1) {
            int y = __shfl_up_sync(0xffffffffu, x, off);
            if (lane >= off) x += y;
        }
        if (lane == 31) sws[wid] = x;
        __syncthreads();
        if (wid == 0) {
            int y = sws[lane];
#pragma unroll
            for (int off = 1; off < 32; off <<= 1) {
                int z = __shfl_up_sync(0xffffffffu, y, off);
                if (lane >= off) y += z;
            }
            sws[lane] = y;
            if (lane == 31) chunk_total = y;
        }
        __syncthreads();
        int incl = x + (wid > 0 ? sws[wid - 1] : 0);
        if (i < NN) {
            int excl = running + incl - v;
            g_rowptr[i] = excl;
            g_cursor[i] = excl;
        }
        running += chunk_total;
        __syncthreads();
    }
    if (threadIdx.x == 0) g_rowptr[NN] = running;
}

// fused: read ei + ea once; eterm1/2; write packed int4 DIRECTLY into CSR slot;
// accumulate set1/set2 segment sums.
__global__ void k_scatter(const int* __restrict__ ei_raw, const float* __restrict__ ea) {
    __shared__ float sve[32];
    if (threadIdx.x < 32) sve[threadIdx.x] = g_ve[threadIdx.x];
    __syncthreads();
    int stride = gridDim.x * blockDim.x;
    int idx64 = g_idx64;
    for (int e = blockIdx.x * blockDim.x + threadIdx.x; e < EE; e += stride) {
        int src, dst;
        if (idx64) {
            const long long* pp = (const long long*)ei_raw;
            src = (int)pp[e]; dst = (int)pp[EE + e];
        } else {
            src = ei_raw[e]; dst = ei_raw[EE + e];
        }
        const float4* ea4 = (const float4*)(ea + (size_t)e * 16);
        float t1 = 0.f, t2 = 0.f;
#pragma unroll
        for (int q = 0; q < 4; q++) {
            float4 v = ea4[q];
            t1 += v.x * sve[q*4+0] + v.y * sve[q*4+1] + v.z * sve[q*4+2] + v.w * sve[q*4+3];
            t2 += v.x * sve[16+q*4+0] + v.y * sve[16+q*4+1] + v.z * sve[16+q*4+2] + v.w * sve[16+q*4+3];
        }
        int pos = atomicAdd(&g_cursor[dst], 1);
        g_csr[pos] = make_int4(src, __float_as_int(t1), __float_as_int(t2), 0);
        atomicAdd(&g_set1[dst], t1);
        atomicAdd(&g_set2[dst], t2);
    }
}

// Tensor-core GEMM (tf32 WMMA): C[64 x 128 tile] = act(A) @ W.
// layer 0: g_g[0] = x @ W ; layer 1: g_g[1] = relu(g_agg[0] + bias) @ W
// A staged via smem (bias+relu+tf32 convert fused); C staged back through the
// same smem for the fused gs/gd epilogue. g_g rows padded to NN_PAD.
__global__ void __launch_bounds__(256) k_gemm_tc(int layer,
                                                 const float* __restrict__ x,
                                                 const float* __restrict__ W,
                                                 const float* __restrict__ bias,
                                                 const float* __restrict__ as,
                                                 const float* __restrict__ ad) {
    __shared__ float As[64 * 128];
    const float* A = (layer == 0) ? x : g_agg[0];
    float* C = g_g[layer];
    int tid = threadIdx.x;
    int wid = tid >> 5, lane = tid & 31;
    int rowBase = blockIdx.x * 64;

    // stage A tile (bias+relu for layer 1), round to tf32
    for (int t = tid; t < 64 * 32; t += 256) {
        int r = t >> 5, c4 = t & 31;
        int row = rowBase + r;
        float4 v = make_float4(0.f, 0.f, 0.f, 0.f);
        if (row < NN) {
            v = ((const float4*)A)[(size_t)row * 32 + c4];
            if (layer == 1) {
                float4 b = ((const float4*)bias)[c4];
                v.x = relu_np(v.x + b.x);
                v.y = relu_np(v.y + b.y);
                v.z = relu_np(v.z + b.z);
                v.w = relu_np(v.w + b.w);
            }
        }
        v.x = wmma::__float_to_tf32(v.x);
        v.y = wmma::__float_to_tf32(v.y);
        v.z = wmma::__float_to_tf32(v.z);
        v.w = wmma::__float_to_tf32(v.w);
        *(float4*)&As[r * 128 + c4 * 4] = v;
    }
    __syncthreads();

    int wr = wid & 3;     // row group (16 rows)
    int wc = wid >> 2;    // col half (64 cols)
    wmma::fragment<wmma::accumulator, 16, 16, 8, float> c_frag[4];
#pragma unroll
    for (int f = 0; f < 4; f++) wmma::fill_fragment(c_frag[f], 0.f);

#pragma unroll
    for (int k = 0; k < 128; k += 8) {
        wmma::fragment<wmma::matrix_a, 16, 16, 8, wmma::precision::tf32, wmma::row_major> a_frag;
        wmma::load_matrix_sync(a_frag, &As[(wr * 16) * 128 + k], 128);
#pragma unroll
        for (int f = 0; f < 4; f++) {
            wmma::fragment<wmma::matrix_b, 16, 16, 8, wmma::precision::tf32, wmma::row_major> b_frag;
            wmma::load_matrix_sync(b_frag, W + (size_t)k * 128 + wc * 64 + f * 16, 128);
#pragma unroll
            for (int i = 0; i < b_frag.num_elements; i++)
                b_frag.x[i] = wmma::__float_to_tf32(b_frag.x[i]);
            wmma::mma_sync(c_frag[f], a_frag, b_frag, c_frag[f]);
        }
    }

    __syncthreads();   // As reuse as C staging
#pragma unroll
    for (int f = 0; f < 4; f++)
        wmma::store_matrix_sync(&As[(wr * 16) * 128 + wc * 64 + f * 16], c_frag[f], 128,
                                wmma::mem_row_major);
    __syncthreads();

    // epilogue: 8 rows per warp; row store + fused gs/gd dot
    float4 as4 = ((const float4*)as)[lane];
    float4 ad4 = ((const float4*)ad)[lane];
#pragma unroll
    for (int rr = 0; rr < 8; rr++) {
        int r = wid * 8 + rr;
        int row = rowBase + r;
        float4 v = *(float4*)&As[r * 128 + lane * 4];
        ((float4*)C)[(size_t)row * 32 + lane] = v;   // padded, always in-bounds
        if (row < NN) {
            float s = v.x * as4.x + v.y * as4.y + v.z * as4.z + v.w * as4.w;
            float d = v.x * ad4.x + v.y * ad4.y + v.z * ad4.z + v.w * ad4.w;
#pragma unroll
            for (int off = 16; off > 0; off >>= 1) {
                s += __shfl_xor_sync(0xffffffffu, s, off);
                d += __shfl_xor_sync(0xffffffffu, d, off);
            }
            if (lane == 0) {
                g_gs[layer][row] = s;
                g_gd[layer][row] = d;
            }
        }
    }
}

// Fused attention softmax + aggregation: one warp per node, zero atomics.
// ex written into g_csr[j].w in pass 1; pass 2 gets (src, ex) in one 16B load.
__global__ void __launch_bounds__(256) k_aggfused(int layer) {
    int node = blockIdx.x * 8 + (threadIdx.x >> 5);
    int lane = threadIdx.x & 31;
    if (node >= NN) return;
    const float* gs  = g_gs[layer];
    const float* gd  = g_gd[layer];
    const float* set = layer ? g_set2 : g_set1;
    const float* gp  = g_g[layer];
    float* aggp      = g_agg[layer];

    int beg = g_rowptr[node], end = g_rowptr[node + 1];
    float gd_i = gd[node];

    float et_self = set[node] / fmaxf(g_deg[node], 1.0f);
    float a_self = gs[node] + gd_i + et_self;
    a_self = a_self > 0.f ? a_self : 0.2f * a_self;
    float ex_self = expf(a_self);

    float densum = 0.f;
    for (int j = beg + lane; j < end; j += 32) {
        int4 c = g_csr[j];
        float et = __int_as_float(layer ? c.z : c.y);
        float a = gs[c.x] + gd_i + et;
        a = a > 0.f ? a : 0.2f * a;
        float ex = expf(a);
        g_csr[j].w = __float_as_int(ex);
        densum += ex;
    }
#pragma unroll
    for (int off = 16; off > 0; off >>= 1)
        densum += __shfl_xor_sync(0xffffffffu, densum, off);
    float inv = 1.0f / (densum + ex_self);

    float w = ex_self * inv;
    float4 v = *(const float4*)(gp + (size_t)node * HH + lane * 4);
    float4 acc = make_float4(w * v.x, w * v.y, w * v.z, w * v.w);

    int j = beg;
    for (; j + 4 <= end; j += 4) {
        int4 c0 = g_csr[j], c1 = g_csr[j+1], c2 = g_csr[j+2], c3 = g_csr[j+3];
        float w0 = __int_as_float(c0.w) * inv, w1 = __int_as_float(c1.w) * inv,
              w2 = __int_as_float(c2.w) * inv, w3 = __int_as_float(c3.w) * inv;
        float4 u0 = *(const float4*)(gp + (size_t)c0.x * HH + lane * 4);
        float4 u1 = *(const float4*)(gp + (size_t)c1.x * HH + lane * 4);
        float4 u2 = *(const float4*)(gp + (size_t)c2.x * HH + lane * 4);
        float4 u3 = *(const float4*)(gp + (size_t)c3.x * HH + lane * 4);
        acc.x += w0*u0.x + w1*u1.x + w2*u2.x + w3*u3.x;
        acc.y += w0*u0.y + w1*u1.y + w2*u2.y + w3*u3.y;
        acc.z += w0*u0.z + w1*u1.z + w2*u2.z + w3*u3.z;
        acc.w += w0*u0.w + w1*u1.w + w2*u2.w + w3*u3.w;
    }
    for (; j < end; j++) {
        int4 c = g_csr[j];
        float wj = __int_as_float(c.w) * inv;
        float4 u = *(const float4*)(gp + (size_t)c.x * HH + lane * 4);
        acc.x += wj * u.x;
        acc.y += wj * u.y;
        acc.z += wj * u.z;
        acc.w += wj * u.w;
    }
    *(float4*)(aggp + (size_t)node * HH + lane * 4) = acc;
}

__global__ void k_hgsum(const float* __restrict__ b2) {
    __shared__ float sh[HH];
    int c = threadIdx.x & 127;
    int half = threadIdx.x >> 7;
    float bb = b2[c];
    float s = 0.f;
    for (int i = blockIdx.x * 2 + half; i < NN; i += gridDim.x * 2)
        s += relu_np(g_agg[1][(size_t)i * HH + c] + bb);
    if (half == 1) sh[c] = s;
    __syncthreads();
    if (half == 0) g_hpart[blockIdx.x * HH + c] = s + sh[c];
}

__global__ void k_head(const float* __restrict__ muW, const float* __restrict__ mub,
                       const float* __restrict__ lvW, const float* __restrict__ lvb,
                       const float* __restrict__ eps,
                       const float* __restrict__ decW, const float* __restrict__ decb,
                       const float* __restrict__ aW1, const float* __restrict__ ab1,
                       const float* __restrict__ aW2, const float* __restrict__ ab2,
                       const float* __restrict__ nW1, const float* __restrict__ nb1,
                       const float* __restrict__ nW2, const float* __restrict__ nb2,
                       float* __restrict__ out) {
    __shared__ float hgm[HH], z[LATD], hd[HH], tmp[HH];
    int t = threadIdx.x;
    if (t < HH) {
        float s = 0.f;
        for (int b = 0; b < HG_BLOCKS; b++) s += g_hpart[b * HH + t];
        hgm[t] = s * (1.0f / (float)NN);
    }
    __syncthreads();
    if (t < LATD) {
        float m = mub[t], l = lvb[t];
        for (int k = 0; k < HH; k++) { m += hgm[k] * muW[k * LATD + t]; l += hgm[k] * lvW[k * LATD + t]; }
        out[MU_OFF + t] = m;
        out[LV_OFF + t] = l;
        z[t] = m + eps[t] * expf(0.5f * l);
    }
    __syncthreads();
    if (t < HH) {
        float s = decb[t];
        for (int j = 0; j < LATD; j++) s += z[j] * decW[j * HH + t];
        hd[t] = relu_np(s);
    }
    __syncthreads();
    if (t < HH) {
        float s = ab1[t];
        for (int k = 0; k < HH; k++) s += hd[k] * aW1[k * HH + t];
        tmp[t] = relu_np(s);
    }
    __syncthreads();
    for (int m = t; m < MAXNODE; m += blockDim.x) {
        float s = ab2[m];
        for (int k = 0; k < HH; k++) s += tmp[k] * aW2[k * MAXNODE + m];
        g_adj_row[m] = s;
    }
    __syncthreads();
    if (t < HH) {
        float s = nb1[t];
        for (int k = 0; k < HH; k++) s += hd[k] * nW1[k * HH + t];
        tmp[t] = relu_np(s);
    }
    __syncthreads();
    if (t < HH) {
        float s = nb2[t];
        for (int k = 0; k < HH; k++) s += tmp[k] * nW2[k * HH + t];
        g_node_row[t] = s;
    }
}

__global__ void k_fill(float4* __restrict__ out4) {
    __shared__ float4 sadj[50];
    __shared__ float4 snd[32];
    int t = threadIdx.x;
    if (t < 50) sadj[t] = ((const float4*)g_adj_row)[t];
    else if (t < 82) snd[t - 50] = ((const float4*)g_node_row)[t - 50];
    __syncthreads();
    const int ADJ4 = ADJ_SZ / 4;
    const int TOT4 = (ADJ_SZ + NODES_SZ) / 4;
    int stride = gridDim.x * blockDim.x;
    for (int i = blockIdx.x * blockDim.x + t; i < TOT4; i += stride) {
        float4 v;
        if (i < ADJ4) v = sadj[i % 50];
        else          v = snd[(i - ADJ4) & 31];
        out4[i] = v;
    }
}

extern "C" void kernel_launch(void* const* d_in, const int* in_sizes, int n_in,
                              void* d_out, int out_size) {
    const float* x   = (const float*)d_in[0];
    const int*   ei  = (const int*)  d_in[1];
    const float* ea  = (const float*)d_in[2];
    const float* eps = (const float*)d_in[3];
    int p = n_in - 26;
    if (p < 4) p = 4;
    if (p > 5) p = (in_sizes[4] == 1) ? 5 : 4;
    const float* W1   = (const float*)d_in[p + 0];
    const float* as1  = (const float*)d_in[p + 1];
    const float* ad1  = (const float*)d_in[p + 2];
    const float* We1  = (const float*)d_in[p + 3];
    const float* ae1  = (const float*)d_in[p + 4];
    const float* b1   = (const float*)d_in[p + 5];
    const float* W2   = (const float*)d_in[p + 6];
    const float* as2  = (const float*)d_in[p + 7];
    const float* ad2  = (const float*)d_in[p + 8];
    const float* We2  = (const float*)d_in[p + 9];
    const float* ae2  = (const float*)d_in[p + 10];
    const float* b2   = (const float*)d_in[p + 11];
    const float* muW  = (const float*)d_in[p + 12];
    const float* mub  = (const float*)d_in[p + 13];
    const float* lvW  = (const float*)d_in[p + 14];
    const float* lvb  = (const float*)d_in[p + 15];
    const float* decW = (const float*)d_in[p + 16];
    const float* decb = (const float*)d_in[p + 17];
    const float* aW1  = (const float*)d_in[p + 18];
    const float* ab1  = (const float*)d_in[p + 19];
    const float* aW2  = (const float*)d_in[p + 20];
    const float* ab2  = (const float*)d_in[p + 21];
    const float* nW1  = (const float*)d_in[p + 22];
    const float* nb1  = (const float*)d_in[p + 23];
    const float* nW2  = (const float*)d_in[p + 24];
    const float* nb2  = (const float*)d_in[p + 25];
    float* out = (float*)d_out;

    k_pre<<<256, 256>>>(ei, We1, ae1, We2, ae2);
    k_deg<<<2048, 256>>>(ei);
    k_prefix<<<1, 1024>>>();
    k_scatter<<<2048, 256>>>(ei, ea);

    int gemm_blocks = NN_PAD / 64;           // 782
    int agg_blocks = (NN + 7) / 8;

    k_gemm_tc<<<gemm_blocks, 256>>>(0, x, W1, b1, as1, ad1);
    k_aggfused<<<agg_blocks, 256>>>(0);

    k_gemm_tc<<<gemm_blocks, 256>>>(1, x, W2, b1, as2, ad2);
    k_aggfused<<<agg_blocks, 256>>>(1);

    k_hgsum<<<HG_BLOCKS, 256>>>(b2);
    k_head<<<1, 256>>>(muW, mub, lvW, lvb, eps, decW, decb,
                       aW1, ab1, aW2, ab2, nW1, nb1, nW2, nb2, out);
    k_fill<<<2048, 256>>>((float4*)out);
}